// round 7
// baseline (speedup 1.0000x reference)
#include <cuda_runtime.h>
#include <cstdint>

// h_t = tanh(x_t @ W_ih^T + b_ih + b_hh + h_{t-1} @ W_hh^T); out = h_{T-1}
// B=4096, T=512, IN=15, HID=20.
//
// ONE WARP PER BATCH: lane j (0..19) owns hidden unit j; lanes 20..31 ride
// along (zero weights). All h/x exchange is warp-local smem, so __syncwarp
// is just an ordering fence — no cross-warp sync at all. 4096 warps total
// -> ~27.7 warps/SM for latency hiding (R6 had only ~9).
// Packed fma.rn.f32x2 along k; x prefetched via register FIFO (distance 3).

#define T_STEPS 512
#define BATCH   4096
#define N_IN    15
#define N_HID   20
#define WPC     8                    // warps (=batches) per CTA
#define THREADS (WPC * 32)           // 256
#define N_CTAS  (BATCH / WPC)        // 512

typedef unsigned long long ull;

__device__ __forceinline__ ull pack2(float lo, float hi) {
    ull r; asm("mov.b64 %0, {%1, %2};" : "=l"(r) : "f"(lo), "f"(hi)); return r;
}
__device__ __forceinline__ ull fma2(ull a, ull b, ull c) {
    ull d; asm("fma.rn.f32x2 %0, %1, %2, %3;" : "=l"(d) : "l"(a), "l"(b), "l"(c)); return d;
}
__device__ __forceinline__ ull add2(ull a, ull b) {
    ull d; asm("add.rn.f32x2 %0, %1, %2;" : "=l"(d) : "l"(a), "l"(b)); return d;
}
__device__ __forceinline__ float hsum2(ull a) {
    float lo, hi; asm("mov.b64 {%0, %1}, %2;" : "=f"(lo), "=f"(hi) : "l"(a));
    return lo + hi;
}
__device__ __forceinline__ float fast_tanh(float z) {
    // tanh(z) = 1 - 2/(exp(2z)+1); ~1e-6 rel err, saturates correctly
    float e = __expf(2.0f * z);
    return 1.0f - __fdividef(2.0f, e + 1.0f);
}

__global__ __launch_bounds__(THREADS, 3)   // cap regs ~85 so occ is grid-limited
void rnn_warp_per_batch(const float* __restrict__ feature,
                        const float* __restrict__ W_ih,
                        const float* __restrict__ W_hh,
                        const float* __restrict__ b_ih,
                        const float* __restrict__ b_hh,
                        float* __restrict__ out)
{
    // per-warp staging rows, double buffered; 16B-aligned rows for LDS.128
    __shared__ __align__(16) float xs[2][WPC][16];  // x_t (15 + zero pad)
    __shared__ __align__(16) float hs[2][WPC][20];  // h_{t-1}

    const int wid  = threadIdx.x >> 5;   // batch slot in CTA
    const int lane = threadIdx.x & 31;
    const int b    = blockIdx.x * WPC + wid;      // < 4096 always (512*8)
    const int j    = lane;                         // hidden unit
    const bool cu  = (j < N_HID);                  // compute lane
    const bool xl  = (lane < N_IN);                // x-staging lane
    const int jc   = cu ? j : 0;                   // clamped row for safe loads

    // ---- pre-pack weights as f32x2 k-pairs; idle lanes get zeros ----
    ull w[18];                                     // [0..7]=W_ih pairs, [8..17]=W_hh pairs
#pragma unroll
    for (int p = 0; p < 7; p++)
        w[p] = pack2(W_ih[jc * N_IN + 2 * p], W_ih[jc * N_IN + 2 * p + 1]);
    w[7] = pack2(W_ih[jc * N_IN + 14], 0.0f);
#pragma unroll
    for (int p = 0; p < 10; p++)
        w[8 + p] = pack2(W_hh[jc * N_HID + 2 * p], W_hh[jc * N_HID + 2 * p + 1]);
    if (!cu) {
#pragma unroll
        for (int p = 0; p < 18; p++) w[p] = 0ull;
    }
    const ull bias2 = cu ? pack2(b_ih[j] + b_hh[j], 0.0f) : 0ull;

    // ---- prologue: h_{-1}=0, x_0 staged, pads zeroed, x_1..x_3 in FIFO ----
    const float* xrow = feature + (size_t)b * T_STEPS * N_IN;
    if (cu) hs[0][wid][j] = 0.0f;
    if (xl) xs[0][wid][lane] = xrow[lane];
    if (lane == N_IN) { xs[0][wid][15] = 0.0f; xs[1][wid][15] = 0.0f; }

    float f1 = xl ? xrow[1 * N_IN + lane] : 0.0f;  // x_{t+1}
    float f2 = xl ? xrow[2 * N_IN + lane] : 0.0f;  // x_{t+2}
    float f3 = xl ? xrow[3 * N_IN + lane] : 0.0f;  // x_{t+3}

    float h = 0.0f;

#pragma unroll 2
    for (int t = 0; t < T_STEPS; t++) {
        const int p = t & 1;
        __syncwarp();   // ordering fence (all traffic is intra-warp)

        // publish x_{t+1}; rotate FIFO; prefetch x_{t+4}
        if (xl) xs[p ^ 1][wid][lane] = f1;
        f1 = f2; f2 = f3;
        f3 = (xl && (t + 4) < T_STEPS) ? xrow[(t + 4) * N_IN + lane] : 0.0f;

        // gather x_t (4x LDS.128) and h_{t-1} (5x LDS.128), broadcast reads
        ull xp[8], hp[10];
        {
            const ulonglong2* xv = (const ulonglong2*)xs[p][wid];
            ulonglong2 v0 = xv[0], v1 = xv[1], v2 = xv[2], v3 = xv[3];
            xp[0] = v0.x; xp[1] = v0.y; xp[2] = v1.x; xp[3] = v1.y;
            xp[4] = v2.x; xp[5] = v2.y; xp[6] = v3.x; xp[7] = v3.y;
        }
        {
            const ulonglong2* hv = (const ulonglong2*)hs[p][wid];
            ulonglong2 v0 = hv[0], v1 = hv[1], v2 = hv[2], v3 = hv[3], v4 = hv[4];
            hp[0] = v0.x; hp[1] = v0.y; hp[2] = v1.x; hp[3] = v1.y;
            hp[4] = v2.x; hp[5] = v2.y; hp[6] = v3.x; hp[7] = v3.y;
            hp[8] = v4.x; hp[9] = v4.y;
        }

        // 18 fma2, two chains of depth 9
        ull a = bias2, c = 0ull;
#pragma unroll
        for (int k = 0; k < 8; k++) {
            if (k & 1) c = fma2(xp[k], w[k], c);
            else       a = fma2(xp[k], w[k], a);
        }
#pragma unroll
        for (int k = 0; k < 10; k++) {
            if (k & 1) c = fma2(hp[k], w[8 + k], c);
            else       a = fma2(hp[k], w[8 + k], a);
        }
        const float z = hsum2(add2(a, c));

        h = fast_tanh(z);

        if (cu) hs[p ^ 1][wid][j] = h;
    }

    if (cu) out[b * N_HID + j] = h;
}

extern "C" void kernel_launch(void* const* d_in, const int* in_sizes, int n_in,
                              void* d_out, int out_size)
{
    const float* feature = (const float*)d_in[0];
    const float* W_ih    = (const float*)d_in[1];
    const float* W_hh    = (const float*)d_in[2];
    const float* b_ih    = (const float*)d_in[3];
    const float* b_hh    = (const float*)d_in[4];
    float* out = (float*)d_out;

    rnn_warp_per_batch<<<N_CTAS, THREADS>>>(feature, W_ih, W_hh, b_ih, b_hh, out);
}

// round 9
// speedup vs baseline: 1.5404x; 1.5404x over previous
#include <cuda_runtime.h>
#include <cstdint>

// h_t = tanh(x_t @ W_ih^T + b_ih + b_hh + h_{t-1} @ W_hh^T); out = h_{T-1}
// B=4096, T=512, IN=15, HID=20.
//
// Thread = (batch, hidden unit): every lane does 35 distinct MACs (18 fma2).
// CTA = 64 threads = 2 warps = 3 batches  -> per-step sync is a CHEAP 2-warp
// bar.sync (~7cyc), and ~10 independent CTAs/SM provide desynchronized
// streams so chain latency overlaps with other CTAs' issue.
// 1366 CTAs, launch_bounds(64,10): single wave, ~18.5 warps/SM.
// f32x2 packed FMAs; x prefetched via distance-3 register FIFO.

#define T_STEPS 512
#define BATCH   4096
#define N_IN    15
#define N_HID   20
#define BPC     3                      // batches per CTA
#define THREADS 64                     // 2 warps; threads 60..63 idle-compute
#define N_CTAS  ((BATCH + BPC - 1) / BPC)   // 1366

typedef unsigned long long ull;

__device__ __forceinline__ ull pack2(float lo, float hi) {
    ull r; asm("mov.b64 %0, {%1, %2};" : "=l"(r) : "f"(lo), "f"(hi)); return r;
}
__device__ __forceinline__ ull fma2(ull a, ull b, ull c) {
    ull d; asm("fma.rn.f32x2 %0, %1, %2, %3;" : "=l"(d) : "l"(a), "l"(b), "l"(c)); return d;
}
__device__ __forceinline__ ull add2(ull a, ull b) {
    ull d; asm("add.rn.f32x2 %0, %1, %2;" : "=l"(d) : "l"(a), "l"(b)); return d;
}
__device__ __forceinline__ float hsum2(ull a) {
    float lo, hi; asm("mov.b64 {%0, %1}, %2;" : "=f"(lo), "=f"(hi) : "l"(a));
    return lo + hi;
}
__device__ __forceinline__ float fast_tanh(float z) {
    // tanh(z) = 1 - 2/(exp(2z)+1): FMUL, MUFU.EX2, FADD, MUFU.RCP, FFMA
    float e = __expf(2.0f * z);
    return 1.0f - __fdividef(2.0f, e + 1.0f);
}

__global__ __launch_bounds__(THREADS, 10)
void rnn_cta64_kernel(const float* __restrict__ feature,
                      const float* __restrict__ W_ih,
                      const float* __restrict__ W_hh,
                      const float* __restrict__ b_ih,
                      const float* __restrict__ b_hh,
                      float* __restrict__ out)
{
    // rows padded to 20 floats (80B): batch rows 0/80/160B -> disjoint banks.
    __shared__ __align__(16) float xs[2][BPC][20];  // x_t in [0..14], [15]=0 pad
    __shared__ __align__(16) float hs[2][BPC][20];  // h_{t-1}

    const int tid = threadIdx.x;
    const bool work = (tid < BPC * N_HID);          // threads 60..63 idle-compute
    const int g  = work ? (tid / N_HID) : 0;        // batch slot 0..2
    const int j  = work ? (tid % N_HID) : 0;        // hidden unit 0..19
    const int b  = blockIdx.x * BPC + g;
    const bool valid = work && (b < BATCH);
    const bool xst   = valid && (j < N_IN);         // this thread stages x[j]

    // ---- pre-pack weights as f32x2 k-pairs (loop-invariant regs) ----
    ull wx[8], wh[10];
#pragma unroll
    for (int p = 0; p < 7; p++)
        wx[p] = pack2(W_ih[j * N_IN + 2 * p], W_ih[j * N_IN + 2 * p + 1]);
    wx[7] = pack2(W_ih[j * N_IN + 14], 0.0f);
#pragma unroll
    for (int p = 0; p < 10; p++)
        wh[p] = pack2(W_hh[j * N_HID + 2 * p], W_hh[j * N_HID + 2 * p + 1]);
    const ull bias2 = pack2(b_ih[j] + b_hh[j], 0.0f);

    // ---- prologue: h_{-1}=0, x_0 staged, x_1..x_3 in register FIFO ----
    const float* xrow = feature + (size_t)(valid ? b : 0) * T_STEPS * N_IN;
    if (work) {
        hs[0][g][j] = 0.0f;
        if (j < N_IN) xs[0][g][j] = valid ? xrow[j] : 0.0f;
        if (j >= N_IN) { xs[0][g][j] = 0.0f; xs[1][g][j] = 0.0f; }  // pads both bufs
    }
    float f1 = xst ? xrow[1 * N_IN + j] : 0.0f;
    float f2 = xst ? xrow[2 * N_IN + j] : 0.0f;
    float f3 = xst ? xrow[3 * N_IN + j] : 0.0f;

    float h = 0.0f;

#pragma unroll 2
    for (int t = 0; t < T_STEPS; t++) {
        const int p = t & 1;
        __syncthreads();   // 2-warp barrier: buf p ready, prev readers of p^1 done

        // publish x_{t+1} into buf p^1; rotate FIFO; prefetch x_{t+4}
        if (xst) xs[p ^ 1][g][j] = f1;
        f1 = f2; f2 = f3;
        f3 = (xst && (t + 4) < T_STEPS) ? xrow[(t + 4) * N_IN + j] : 0.0f;

        // gather x_t (4x LDS.128) and h_{t-1} (5x LDS.128) from buf p
        ull xp[8], hp[10];
        {
            const ulonglong2* xv = (const ulonglong2*)xs[p][g];
            ulonglong2 v0 = xv[0], v1 = xv[1], v2 = xv[2], v3 = xv[3];
            xp[0] = v0.x; xp[1] = v0.y; xp[2] = v1.x; xp[3] = v1.y;
            xp[4] = v2.x; xp[5] = v2.y; xp[6] = v3.x; xp[7] = v3.y;
        }
        {
            const ulonglong2* hv = (const ulonglong2*)hs[p][g];
            ulonglong2 v0 = hv[0], v1 = hv[1], v2 = hv[2], v3 = hv[3], v4 = hv[4];
            hp[0] = v0.x; hp[1] = v0.y; hp[2] = v1.x; hp[3] = v1.y;
            hp[4] = v2.x; hp[5] = v2.y; hp[6] = v3.x; hp[7] = v3.y;
            hp[8] = v4.x; hp[9] = v4.y;
        }

        // 18 fma2 on two chains (depth 9), then horizontal sum
        ull a = bias2, c = 0ull;
#pragma unroll
        for (int k = 0; k < 8; k++) {
            if (k & 1) c = fma2(xp[k], wx[k], c);
            else       a = fma2(xp[k], wx[k], a);
        }
#pragma unroll
        for (int k = 0; k < 10; k++) {
            if (k & 1) c = fma2(hp[k], wh[k], c);
            else       a = fma2(hp[k], wh[k], a);
        }
        const float z = hsum2(add2(a, c));

        h = fast_tanh(z);

        if (work) hs[p ^ 1][g][j] = h;   // publish h_t for step t+1
    }

    if (valid) out[b * N_HID + j] = h;
}

extern "C" void kernel_launch(void* const* d_in, const int* in_sizes, int n_in,
                              void* d_out, int out_size)
{
    const float* feature = (const float*)d_in[0];
    const float* W_ih    = (const float*)d_in[1];
    const float* W_hh    = (const float*)d_in[2];
    const float* b_ih    = (const float*)d_in[3];
    const float* b_hh    = (const float*)d_in[4];
    float* out = (float*)d_out;

    rnn_cta64_kernel<<<N_CTAS, THREADS>>>(feature, W_ih, W_hh, b_ih, b_hh, out);
}

// round 10
// speedup vs baseline: 1.8795x; 1.2201x over previous
#include <cuda_runtime.h>
#include <cstdint>

// h_t = tanh(x_t @ W_ih^T + b_ih + b_hh + h_{t-1} @ W_hh^T); out = h_{T-1}
// B=4096, T=512, IN=15, HID=20.
//
// KEY INSIGHT (from R1/R9 ncu arithmetic): the binder was the SM-wide smem
// crossbar — LDS.128 pays ~4 wavefronts/warp, and re-reading all 35 operands
// per thread per step saturates it (~666 cyc/SM/step in R9).
// Fix: h never touches smem. Each lane keeps its 2 h values in REGISTERS and
// the 10-pair gather is done with shfl.sync (register exchange, no crossbar).
// x keeps the cheap warp-local smem broadcast path (4 LDS.128/step).
// CTA = 1 warp (3 batches): no CTA barrier at all; 1366 independent CTAs.

#define T_STEPS 512
#define BATCH   4096
#define N_IN    15
#define N_HID   20
#define BPW     3                      // batches per warp
#define THREADS 32
#define N_CTAS  ((BATCH + BPW - 1) / BPW)   // 1366
#define FULL    0xffffffffu

typedef unsigned long long ull;

__device__ __forceinline__ ull pack2(float lo, float hi) {
    ull r; asm("mov.b64 %0, {%1, %2};" : "=l"(r) : "f"(lo), "f"(hi)); return r;
}
__device__ __forceinline__ ull fma2(ull a, ull b, ull c) {
    ull d; asm("fma.rn.f32x2 %0, %1, %2, %3;" : "=l"(d) : "l"(a), "l"(b), "l"(c)); return d;
}
__device__ __forceinline__ ull add2(ull a, ull b) {
    ull d; asm("add.rn.f32x2 %0, %1, %2;" : "=l"(d) : "l"(a), "l"(b)); return d;
}
__device__ __forceinline__ float hsum2(ull a) {
    float lo, hi; asm("mov.b64 {%0, %1}, %2;" : "=f"(lo), "=f"(hi) : "l"(a));
    return lo + hi;
}
__device__ __forceinline__ float fast_tanh(float z) {
    // tanh(z) = 1 - 2/(exp(2z)+1): FMUL, MUFU.EX2, FADD, MUFU.RCP, FFMA
    float e = __expf(2.0f * z);
    return 1.0f - __fdividef(2.0f, e + 1.0f);
}

__global__ __launch_bounds__(THREADS, 10)
void rnn_shfl_kernel(const float* __restrict__ feature,
                     const float* __restrict__ W_ih,
                     const float* __restrict__ W_hh,
                     const float* __restrict__ b_ih,
                     const float* __restrict__ b_hh,
                     float* __restrict__ out)
{
    // ONLY x goes through smem (warp-local, double buffered, 16B-aligned rows)
    __shared__ __align__(16) float xs[2][BPW][16];   // x_t in [0..14], [15]=0

    const int lane = threadIdx.x & 31;
    const int g    = lane / 10;                  // 0..2 batch slot (3 = riders)
    const int tl   = lane % 10;
    const bool active = (g < BPW);               // lanes 30,31 ride along
    const int  gc  = active ? g : 0;
    const int  base = gc * 10;                   // first lane of this group
    const int  b   = blockIdx.x * BPW + gc;
    const bool valid = active && (b < BATCH);
    const bool xst   = valid;                    // all 10 group lanes stage x
    const int j0 = 2 * tl, j1 = 2 * tl + 1;      // hidden units (tl<=9 -> <=19)

    // ---- loop-invariant packed weights (f32x2 k-pairs) ----
    ull wx0[8], wx1[8], wh0[10], wh1[10];
#pragma unroll
    for (int p = 0; p < 7; p++) {
        wx0[p] = pack2(W_ih[j0 * N_IN + 2 * p], W_ih[j0 * N_IN + 2 * p + 1]);
        wx1[p] = pack2(W_ih[j1 * N_IN + 2 * p], W_ih[j1 * N_IN + 2 * p + 1]);
    }
    wx0[7] = pack2(W_ih[j0 * N_IN + 14], 0.0f);
    wx1[7] = pack2(W_ih[j1 * N_IN + 14], 0.0f);
#pragma unroll
    for (int p = 0; p < 10; p++) {
        wh0[p] = pack2(W_hh[j0 * N_HID + 2 * p], W_hh[j0 * N_HID + 2 * p + 1]);
        wh1[p] = pack2(W_hh[j1 * N_HID + 2 * p], W_hh[j1 * N_HID + 2 * p + 1]);
    }
    const ull bias2_0 = pack2(b_ih[j0] + b_hh[j0], 0.0f);
    const ull bias2_1 = pack2(b_ih[j1] + b_hh[j1], 0.0f);

    // ---- prologue: x_0 staged, pads zeroed, x_1..x_3 in register FIFO ----
    const float* xrow = feature + (size_t)(valid ? b : 0) * T_STEPS * N_IN;
    if (xst) {
        xs[0][gc][tl] = xrow[tl];
        if (tl < 5) xs[0][gc][10 + tl] = xrow[10 + tl];
        if (tl == 0) { xs[0][gc][15] = 0.0f; xs[1][gc][15] = 0.0f; }
    }
    float fa1 = xst ? xrow[1 * N_IN + tl] : 0.0f;
    float fb1 = (xst && tl < 5) ? xrow[1 * N_IN + 10 + tl] : 0.0f;
    float fa2 = xst ? xrow[2 * N_IN + tl] : 0.0f;
    float fb2 = (xst && tl < 5) ? xrow[2 * N_IN + 10 + tl] : 0.0f;
    float fa3 = xst ? xrow[3 * N_IN + tl] : 0.0f;
    float fb3 = (xst && tl < 5) ? xrow[3 * N_IN + 10 + tl] : 0.0f;

    float h0 = 0.0f, h1 = 0.0f;    // this lane's two hidden units (REGISTERS)

#pragma unroll 2
    for (int t = 0; t < T_STEPS; t++) {
        const int p = t & 1;
        __syncwarp();   // order prev STS(buf p) before LDS(buf p), WAR on p^1

        // publish x_{t+1}; rotate FIFO; prefetch x_{t+4}
        if (xst) {
            xs[p ^ 1][gc][tl] = fa1;
            if (tl < 5) xs[p ^ 1][gc][10 + tl] = fb1;
        }
        fa1 = fa2; fb1 = fb2;
        fa2 = fa3; fb2 = fb3;
        if (xst && (t + 4) < T_STEPS) {
            fa3 = xrow[(t + 4) * N_IN + tl];
            fb3 = (tl < 5) ? xrow[(t + 4) * N_IN + 10 + tl] : 0.0f;
        } else { fa3 = 0.0f; fb3 = 0.0f; }

        // x_t gather: 4x LDS.128 (the ONLY smem reads per step)
        ull xp[8];
        {
            const ulonglong2* xv = (const ulonglong2*)xs[p][gc];
            ulonglong2 v0 = xv[0], v1 = xv[1], v2 = xv[2], v3 = xv[3];
            xp[0] = v0.x; xp[1] = v0.y; xp[2] = v1.x; xp[3] = v1.y;
            xp[4] = v2.x; xp[5] = v2.y; xp[6] = v3.x; xp[7] = v3.y;
        }

        // h_{t-1} gather: register exchange via shfl.sync — no crossbar.
        // Source lanes base..base+9 hold pairs (h[2s], h[2s+1]).
        ull hp[10];
#pragma unroll
        for (int s = 0; s < 10; s++) {
            float lo = __shfl_sync(FULL, h0, base + s);
            float hi = __shfl_sync(FULL, h1, base + s);
            hp[s] = pack2(lo, hi);
        }

        // 36 fma2 over 4 chains (depth ~9 each)
        ull a0 = bias2_0, c0 = 0ull, a1 = bias2_1, c1 = 0ull;
#pragma unroll
        for (int k = 0; k < 8; k++) {
            if (k & 1) { c0 = fma2(xp[k], wx0[k], c0); c1 = fma2(xp[k], wx1[k], c1); }
            else       { a0 = fma2(xp[k], wx0[k], a0); a1 = fma2(xp[k], wx1[k], a1); }
        }
#pragma unroll
        for (int k = 0; k < 10; k++) {
            if (k & 1) { c0 = fma2(hp[k], wh0[k], c0); c1 = fma2(hp[k], wh1[k], c1); }
            else       { a0 = fma2(hp[k], wh0[k], a0); a1 = fma2(hp[k], wh1[k], a1); }
        }
        const float z0 = hsum2(add2(a0, c0));
        const float z1 = hsum2(add2(a1, c1));

        h0 = fast_tanh(z0);        // new h stays in registers; next step's
        h1 = fast_tanh(z1);        // shfl.sync reads it directly
    }

    if (valid) {
        // (b*20 + 2*tl)*4B is 8B-aligned -> STG.64
        *(float2*)&out[b * N_HID + j0] = make_float2(h0, h1);
    }
}

extern "C" void kernel_launch(void* const* d_in, const int* in_sizes, int n_in,
                              void* d_out, int out_size)
{
    const float* feature = (const float*)d_in[0];
    const float* W_ih    = (const float*)d_in[1];
    const float* W_hh    = (const float*)d_in[2];
    const float* b_ih    = (const float*)d_in[3];
    const float* b_hh    = (const float*)d_in[4];
    float* out = (float*)d_out;

    rnn_shfl_kernel<<<N_CTAS, THREADS>>>(feature, W_ih, W_hh, b_ih, b_hh, out);
}